// round 1
// baseline (speedup 1.0000x reference)
#include <cuda_runtime.h>
#include <cuda_bf16.h>
#include <math.h>

#define NN 200000
#define EE 6400000
#define GG 2000

// Scratch: state double buffers padded to 16 floats/row (64B => aligned vec gathers/reds),
// padded coords (float4 gather), graph accumulator padded to 12 floats/row (16B-aligned v4 reds).
__device__ __align__(16) float4 g_S0[NN * 4];
__device__ __align__(16) float4 g_S1[NN * 4];
__device__ __align__(16) float4 g_c4[NN];
__device__ __align__(16) float  g_gs[GG * 12];

// Accurate-enough tanh: exp-based, abs err ~1e-7.
__device__ __forceinline__ float tanh_acc(float x) {
    float ax = fabsf(x);
    float e;
    // e = exp(-2*ax) = 2^(-2*ax*log2(e))
    asm("ex2.approx.f32 %0, %1;" : "=f"(e) : "f"(ax * -2.8853900817779268f));
    float r;
    asm("rcp.approx.f32 %0, %1;" : "=f"(r) : "f"(1.0f + e));
    float t = (1.0f - e) * r;
    return copysignf(t, x);
}

__device__ __forceinline__ float softplus_acc(float x) {
    return log1pf(expf(-fabsf(x))) + fmaxf(x, 0.0f);
}

// Init: zero S1 (round-0 accumulator), zero graph accumulator, build padded coords.
__global__ void init_kernel(const float* __restrict__ coords) {
    int i = blockIdx.x * blockDim.x + threadIdx.x;
    if (i < NN * 4) g_S1[i] = make_float4(0.f, 0.f, 0.f, 0.f);
    if (i < NN)     g_c4[i] = make_float4(coords[3 * i], coords[3 * i + 1], coords[3 * i + 2], 0.f);
    if (i < GG * 12) g_gs[i] = 0.f;
}

__global__ void copy_kernel(const float4* __restrict__ src, float4* __restrict__ dst) {
    int i = blockIdx.x * blockDim.x + threadIdx.x;
    if (i < NN * 4) dst[i] = src[i];
}

template <bool FIRST>
__global__ void edge_kernel(const int* __restrict__ nf, const int* __restrict__ nt,
                            const float* __restrict__ el, const float* __restrict__ ev,
                            const float* __restrict__ Wm, const float* __restrict__ bm,
                            const float4* __restrict__ Sin, float4* __restrict__ Sout) {
    __shared__ __align__(16) float sW[14 * 12];
    __shared__ __align__(16) float sB[12];
    int tid = threadIdx.x;
    if (tid < 140) sW[(tid / 10) * 12 + (tid % 10)] = Wm[tid];
    if (tid < 10)  sB[tid] = bm[tid];
    __syncthreads();

    int e = blockIdx.x * blockDim.x + tid;
    if (e >= EE) return;

    int from = nf[e];
    int to   = nt[e];
    float4 cf = g_c4[from];
    float4 ct = g_c4[to];
    float e0 = ev[3 * e], e1 = ev[3 * e + 1], e2 = ev[3 * e + 2];

    float g0 = el[e];
    float g1 = fabsf(cf.x) + fabsf(cf.y) + fabsf(cf.z);
    float g2 = cf.x * ct.x + cf.y * ct.y + cf.z * ct.z;
    float g3 = cf.x * e0 + cf.y * e1 + cf.z * e2;

    float acc[10];
#pragma unroll
    for (int j = 0; j < 10; j++) {
        acc[j] = sB[j] + g0 * sW[10 * 12 + j] + g1 * sW[11 * 12 + j]
                       + g2 * sW[12 * 12 + j] + g3 * sW[13 * 12 + j];
    }

    if (!FIRST) {
        const float4* srow = Sin + from * 4;
        float4 a = srow[0], b = srow[1], c = srow[2];
        float s[10] = {a.x, a.y, a.z, a.w, b.x, b.y, b.z, b.w, c.x, c.y};
#pragma unroll
        for (int i = 0; i < 10; i++) {
#pragma unroll
            for (int j = 0; j < 10; j++) acc[j] += s[i] * sW[i * 12 + j];
        }
    }

#pragma unroll
    for (int j = 0; j < 10; j++) acc[j] = tanh_acc(acc[j]);

    float* dst = (float*)(Sout + to * 4);
    asm volatile("red.global.add.v4.f32 [%0], {%1,%2,%3,%4};"
                 :: "l"(dst), "f"(acc[0]), "f"(acc[1]), "f"(acc[2]), "f"(acc[3]) : "memory");
    asm volatile("red.global.add.v4.f32 [%0], {%1,%2,%3,%4};"
                 :: "l"(dst + 4), "f"(acc[4]), "f"(acc[5]), "f"(acc[6]), "f"(acc[7]) : "memory");
    asm volatile("red.global.add.v2.f32 [%0], {%1,%2};"
                 :: "l"(dst + 8), "f"(acc[8]), "f"(acc[9]) : "memory");
}

__global__ void node_kernel(const int* __restrict__ ngi, const float4* __restrict__ S) {
    int i = blockIdx.x * blockDim.x + threadIdx.x;
    if (i >= NN) return;
    int g = ngi[i];
    float4 a = S[i * 4], b = S[i * 4 + 1], c = S[i * 4 + 2];
    float* dst = g_gs + g * 12;
    asm volatile("red.global.add.v4.f32 [%0], {%1,%2,%3,%4};"
                 :: "l"(dst), "f"(a.x), "f"(a.y), "f"(a.z), "f"(a.w) : "memory");
    asm volatile("red.global.add.v4.f32 [%0], {%1,%2,%3,%4};"
                 :: "l"(dst + 4), "f"(b.x), "f"(b.y), "f"(b.z), "f"(b.w) : "memory");
    asm volatile("red.global.add.v2.f32 [%0], {%1,%2};"
                 :: "l"(dst + 8), "f"(c.x), "f"(c.y) : "memory");
}

__global__ void out_kernel(const float* __restrict__ Wo, const float* __restrict__ bo,
                           float* __restrict__ out) {
    int g = blockIdx.x * blockDim.x + threadIdx.x;
    if (g >= GG) return;
    float ev[4];
#pragma unroll
    for (int k = 0; k < 4; k++) ev[k] = bo[k];
#pragma unroll
    for (int j = 0; j < 10; j++) {
        float s = g_gs[g * 12 + j];
#pragma unroll
        for (int k = 0; k < 4; k++) ev[k] += s * Wo[j * 4 + k];
    }
    out[4 * g + 0] = ev[0];
    out[4 * g + 1] = softplus_acc(ev[1]);
    out[4 * g + 2] = softplus_acc(ev[2]) + 1.0f;
    out[4 * g + 3] = softplus_acc(ev[3]);
}

extern "C" void kernel_launch(void* const* d_in, const int* in_sizes, int n_in,
                              void* d_out, int out_size) {
    const float* coords = (const float*)d_in[0];
    const float* el     = (const float*)d_in[1];
    const float* evv    = (const float*)d_in[2];
    const float* Wm     = (const float*)d_in[3];
    const float* bm     = (const float*)d_in[4];
    const float* Wo     = (const float*)d_in[5];
    const float* bo     = (const float*)d_in[6];
    const int*   nf     = (const int*)d_in[7];
    const int*   nt     = (const int*)d_in[8];
    const int*   ngi    = (const int*)d_in[9];
    float* out = (float*)d_out;

    float4 *S0, *S1;
    cudaGetSymbolAddress((void**)&S0, g_S0);
    cudaGetSymbolAddress((void**)&S1, g_S1);

    const int TB = 256;
    int grid_init = (NN * 4 + TB - 1) / TB;
    int grid_edge = (EE + TB - 1) / TB;
    int grid_node = (NN + TB - 1) / TB;
    int grid_out  = (GG + TB - 1) / TB;

    // round 0: state = 0, accumulate into S1
    init_kernel<<<grid_init, TB>>>(coords);
    edge_kernel<true><<<grid_edge, TB>>>(nf, nt, el, evv, Wm, bm, S0, S1);
    // round 1: read S1, accumulate into S0 := S1
    copy_kernel<<<grid_init, TB>>>(S1, S0);
    edge_kernel<false><<<grid_edge, TB>>>(nf, nt, el, evv, Wm, bm, S1, S0);
    // round 2: read S0, accumulate into S1 := S0
    copy_kernel<<<grid_init, TB>>>(S0, S1);
    edge_kernel<false><<<grid_edge, TB>>>(nf, nt, el, evv, Wm, bm, S0, S1);
    // graph reduce + output head
    node_kernel<<<grid_node, TB>>>(ngi, S1);
    out_kernel<<<grid_out, TB>>>(Wo, bo, out);
}

// round 4
// speedup vs baseline: 1.1614x; 1.1614x over previous
#include <cuda_runtime.h>
#include <cuda_bf16.h>
#include <math.h>

#define NN 200000
#define EE 6400000
#define GG 2000
#define ROW 16   // floats per state row (64B): [0..7] v8, [8..9] v2, rest pad

__device__ __align__(256) float  g_S0[NN * ROW];
__device__ __align__(256) float  g_S1[NN * ROW];
__device__ __align__(16)  float4 g_c4[NN];
__device__ __align__(256) float  g_gs[GG * ROW];
__device__ __align__(16)  float4 g_geo[EE];

// Accurate tanh via ex2+rcp, abs err ~1e-7.
__device__ __forceinline__ float tanh_acc(float x) {
    float ax = fabsf(x);
    float e;
    asm("ex2.approx.f32 %0, %1;" : "=f"(e) : "f"(ax * -2.8853900817779268f));
    float r;
    asm("rcp.approx.f32 %0, %1;" : "=f"(r) : "f"(1.0f + e));
    return copysignf((1.0f - e) * r, x);
}

__device__ __forceinline__ float softplus_acc(float x) {
    return log1pf(expf(-fabsf(x))) + fmaxf(x, 0.0f);
}

__device__ __forceinline__ void ld_v8(const float* p, float* s) {
    asm("ld.global.nc.v8.f32 {%0,%1,%2,%3,%4,%5,%6,%7}, [%8];"
        : "=f"(s[0]), "=f"(s[1]), "=f"(s[2]), "=f"(s[3]),
          "=f"(s[4]), "=f"(s[5]), "=f"(s[6]), "=f"(s[7])
        : "l"(p));
}
__device__ __forceinline__ void red_v4(float* p, float a, float b, float c, float d) {
    asm volatile("red.global.add.v4.f32 [%0], {%1,%2,%3,%4};"
                 :: "l"(p), "f"(a), "f"(b), "f"(c), "f"(d) : "memory");
}
__device__ __forceinline__ void red_v2(float* p, float a, float b) {
    asm volatile("red.global.add.v2.f32 [%0], {%1,%2};"
                 :: "l"(p), "f"(a), "f"(b) : "memory");
}
__device__ __forceinline__ void red_row(float* dst, const float* a) {
    red_v4(dst,     a[0], a[1], a[2], a[3]);
    red_v4(dst + 4, a[4], a[5], a[6], a[7]);
    red_v2(dst + 8, a[8], a[9]);
}

__global__ void init_kernel(const float* __restrict__ coords) {
    int i = blockIdx.x * blockDim.x + threadIdx.x;
    if (i < NN * ROW) g_S1[i] = 0.f;
    if (i < NN)       g_c4[i] = make_float4(coords[3*i], coords[3*i+1], coords[3*i+2], 0.f);
    if (i < GG * ROW) g_gs[i] = 0.f;
}

__global__ void copy_kernel(const float4* __restrict__ src, float4* __restrict__ dst) {
    int i = blockIdx.x * blockDim.x + threadIdx.x;
    if (i < NN * 4) dst[i] = src[i];
}

// Round 0: state == 0. Computes geo, writes it for later rounds, does msg + scatter.
__global__ void edge0_kernel(const int* __restrict__ nf, const int* __restrict__ nt,
                             const float* __restrict__ el, const float* __restrict__ ev,
                             const float* __restrict__ Wm, const float* __restrict__ bm,
                             float* __restrict__ Sout) {
    __shared__ float sW[140];
    __shared__ float sB[10];
    int tid = threadIdx.x;
    if (tid < 140) sW[tid] = Wm[tid];
    if (tid < 10)  sB[tid] = bm[tid];
    __syncthreads();

    int e = blockIdx.x * blockDim.x + tid;
    if (e >= EE) return;

    int from = nf[e];
    int to   = nt[e];
    float4 cf = g_c4[from];
    float4 ct = g_c4[to];
    float e0 = ev[3*e], e1 = ev[3*e+1], e2 = ev[3*e+2];

    float4 g;
    g.x = el[e];
    g.y = fabsf(cf.x) + fabsf(cf.y) + fabsf(cf.z);
    g.z = cf.x*ct.x + cf.y*ct.y + cf.z*ct.z;
    g.w = cf.x*e0 + cf.y*e1 + cf.z*e2;
    g_geo[e] = g;

    float acc[10];
#pragma unroll
    for (int j = 0; j < 10; j++)
        acc[j] = tanh_acc(sB[j] + g.x*sW[100+j] + g.y*sW[110+j] + g.z*sW[120+j] + g.w*sW[130+j]);

    red_row(Sout + (size_t)to * ROW, acc);
}

// Rounds 1..2: read materialized geo + gathered state.
__global__ void edge_kernel(const int* __restrict__ nf, const int* __restrict__ nt,
                            const float* __restrict__ Wm, const float* __restrict__ bm,
                            const float* __restrict__ Sin, float* __restrict__ Sout) {
    __shared__ float sW[140];
    __shared__ float sB[10];
    int tid = threadIdx.x;
    if (tid < 140) sW[tid] = Wm[tid];
    if (tid < 10)  sB[tid] = bm[tid];
    __syncthreads();

    int e = blockIdx.x * blockDim.x + tid;
    if (e >= EE) return;

    int from = nf[e];
    int to   = nt[e];

    const float* srow = Sin + (size_t)from * ROW;
    float s[10];
    ld_v8(srow, s);
    asm("ld.global.nc.v2.f32 {%0,%1}, [%2];" : "=f"(s[8]), "=f"(s[9]) : "l"(srow + 8));

    float4 g = g_geo[e];

    float acc[10];
#pragma unroll
    for (int j = 0; j < 10; j++)
        acc[j] = sB[j] + g.x*sW[100+j] + g.y*sW[110+j] + g.z*sW[120+j] + g.w*sW[130+j];
#pragma unroll
    for (int i = 0; i < 10; i++) {
#pragma unroll
        for (int j = 0; j < 10; j++) acc[j] += s[i] * sW[i*10+j];
    }
#pragma unroll
    for (int j = 0; j < 10; j++) acc[j] = tanh_acc(acc[j]);

    red_row(Sout + (size_t)to * ROW, acc);
}

__global__ void node_kernel(const int* __restrict__ ngi, const float* __restrict__ S) {
    int i = blockIdx.x * blockDim.x + threadIdx.x;
    if (i >= NN) return;
    int g = ngi[i];
    const float* srow = S + (size_t)i * ROW;
    float s[10];
    ld_v8(srow, s);
    asm("ld.global.nc.v2.f32 {%0,%1}, [%2];" : "=f"(s[8]), "=f"(s[9]) : "l"(srow + 8));
    red_row(g_gs + (size_t)g * ROW, s);
}

__global__ void out_kernel(const float* __restrict__ Wo, const float* __restrict__ bo,
                           float* __restrict__ out) {
    int g = blockIdx.x * blockDim.x + threadIdx.x;
    if (g >= GG) return;
    float ev[4];
#pragma unroll
    for (int k = 0; k < 4; k++) ev[k] = bo[k];
#pragma unroll
    for (int j = 0; j < 10; j++) {
        float s = g_gs[g * ROW + j];
#pragma unroll
        for (int k = 0; k < 4; k++) ev[k] += s * Wo[j*4+k];
    }
    out[4*g+0] = ev[0];
    out[4*g+1] = softplus_acc(ev[1]);
    out[4*g+2] = softplus_acc(ev[2]) + 1.0f;
    out[4*g+3] = softplus_acc(ev[3]);
}

extern "C" void kernel_launch(void* const* d_in, const int* in_sizes, int n_in,
                              void* d_out, int out_size) {
    const float* coords = (const float*)d_in[0];
    const float* el     = (const float*)d_in[1];
    const float* evv    = (const float*)d_in[2];
    const float* Wm     = (const float*)d_in[3];
    const float* bm     = (const float*)d_in[4];
    const float* Wo     = (const float*)d_in[5];
    const float* bo     = (const float*)d_in[6];
    const int*   nf     = (const int*)d_in[7];
    const int*   nt     = (const int*)d_in[8];
    const int*   ngi    = (const int*)d_in[9];
    float* out = (float*)d_out;

    float *S0, *S1;
    cudaGetSymbolAddress((void**)&S0, g_S0);
    cudaGetSymbolAddress((void**)&S1, g_S1);

    const int TB = 256;
    int grid_init = (NN * ROW + TB - 1) / TB;
    int grid_copy = (NN * 4 + TB - 1) / TB;
    int grid_edge = (EE + TB - 1) / TB;
    int grid_node = (NN + TB - 1) / TB;
    int grid_out  = (GG + TB - 1) / TB;

    // round 0: state = 0, write geo, accumulate into S1
    init_kernel<<<grid_init, TB>>>(coords);
    edge0_kernel<<<grid_edge, TB>>>(nf, nt, el, evv, Wm, bm, S1);
    // round 1: read S1, accumulate into S0 := S1
    copy_kernel<<<grid_copy, TB>>>((const float4*)S1, (float4*)S0);
    edge_kernel<<<grid_edge, TB>>>(nf, nt, Wm, bm, S1, S0);
    // round 2: read S0, accumulate into S1 := S0
    copy_kernel<<<grid_copy, TB>>>((const float4*)S0, (float4*)S1);
    edge_kernel<<<grid_edge, TB>>>(nf, nt, Wm, bm, S0, S1);
    // graph reduce + output head
    node_kernel<<<grid_node, TB>>>(ngi, S1);
    out_kernel<<<grid_out, TB>>>(Wo, bo, out);
}